// round 2
// baseline (speedup 1.0000x reference)
#include <cuda_runtime.h>
#include <math.h>

#define BN_EPS 1e-5f

// ---------------- scratch (__device__ globals: allocation-free scratch) ----------------
__device__ float g_m1[67108864];   // [1024][32][8][16][16]
__device__ float g_m2[16777216];   // [1024][64][4][8][8]
__device__ float g_m3[4194304];    // [1024][128][2][4][4]
__device__ float g_wT2[55296];     // [32][27][64]  BN-folded
__device__ float g_shift2[64];
__device__ float g_wT3[221184];    // [64][27][128] BN-folded
__device__ float g_shift3[128];
__device__ float g_gw[4096];       // [1024][4] softmax gate weights
__device__ float g_hid[20971520];  // [1024][4*5120] gate-scaled GEGLU hidden

// ---------------- prep: transpose conv weights + fold BN ----------------
template<int WHICH>
__global__ void prep_kernel(const float* __restrict__ w, const float* __restrict__ bias,
                            const float* __restrict__ bng, const float* __restrict__ bnb,
                            const float* __restrict__ bnm, const float* __restrict__ bnv) {
    constexpr int CIN  = (WHICH == 2) ? 32 : 64;
    constexpr int COUT = (WHICH == 2) ? 64 : 128;
    float* wT    = (WHICH == 2) ? g_wT2 : g_wT3;
    float* shift = (WHICH == 2) ? g_shift2 : g_shift3;
    int idx = blockIdx.x * 256 + threadIdx.x;
    const int total = CIN * 27 * COUT;
    if (idx < total) {
        int o   = idx % COUT;
        int r   = idx / COUT;
        int tap = r % 27;
        int c   = r / 27;
        float s = rsqrtf(bnv[o] + BN_EPS) * bng[o];
        wT[idx] = w[((size_t)o * CIN + c) * 27 + tap] * s;
    }
    if (idx < COUT) {
        float s = rsqrtf(bnv[idx] + BN_EPS) * bng[idx];
        shift[idx] = (bias[idx] - bnm[idx]) * s + bnb[idx];
    }
}

// ---------------- conv1: Cin=1 direct, BN+ReLU fused ----------------
// mask layout: [B=1024, F=16, C=1, H=32, W=32]; logical input depth=f.
// out g_m1: [b][o=32][d=8][h=16][w=16]
__global__ void conv1_kernel(const float* __restrict__ mask,
                             const float* __restrict__ w,   // [32,1,3,3,3]
                             const float* __restrict__ bias,
                             const float* __restrict__ bng, const float* __restrict__ bnb,
                             const float* __restrict__ bnm, const float* __restrict__ bnv) {
    __shared__ float ws[32][27];
    __shared__ float sscale[32], sshift[32];
    int t = threadIdx.x;
    if (t < 32) {
        float s = rsqrtf(bnv[t] + BN_EPS) * bng[t];
        sscale[t] = s;
        sshift[t] = (bias[t] - bnm[t]) * s + bnb[t];
    }
    __syncthreads();
    for (int idx = t; idx < 864; idx += 256) {
        int o = idx / 27, tap = idx % 27;
        ws[o][tap] = w[idx] * sscale[o];
    }
    __syncthreads();

    int b = blockIdx.x, d = blockIdx.y;
    int h = t >> 4, wq = t & 15;
    const float* mb = mask + (size_t)b * 16384;

    float v[27];
#pragma unroll
    for (int kd = 0; kd < 3; kd++)
#pragma unroll
        for (int kh = 0; kh < 3; kh++)
#pragma unroll
            for (int kw = 0; kw < 3; kw++) {
                int zd = 2 * d - 1 + kd, zh = 2 * h - 1 + kh, zw = 2 * wq - 1 + kw;
                bool ok = (unsigned)zd < 16u && (unsigned)zh < 32u && (unsigned)zw < 32u;
                v[(kd * 3 + kh) * 3 + kw] = ok ? mb[zd * 1024 + zh * 32 + zw] : 0.f;
            }

    size_t outbase = (size_t)b * 65536 + (size_t)d * 256 + h * 16 + wq;
#pragma unroll
    for (int o = 0; o < 32; o++) {
        float acc = 0.f;
#pragma unroll
        for (int tap = 0; tap < 27; tap++) acc = fmaf(ws[o][tap], v[tap], acc);
        acc += sshift[o];
        g_m1[outbase + (size_t)o * 2048] = fmaxf(acc, 0.f);
    }
}

// ---------------- conv2/conv3 as per-position implicit GEMM ----------------
// out[pos][b, o] = sum_{c,tap} in[b, c, gather(pos,tap)] * wT[c][tap][o]
// tile: M=64 (batch) x N=64 (out ch), micro 4x4, K chunk = 27 (one channel window)
template<int WHICH>
__global__ void conv_gemm_kernel() {
    constexpr int CIN  = (WHICH == 2) ? 32 : 64;
    constexpr int COUT = (WHICH == 2) ? 64 : 128;
    constexpr int DIN  = (WHICH == 2) ? 8 : 4;
    constexpr int HIN  = (WHICH == 2) ? 16 : 8;
    constexpr int WIN  = (WHICH == 2) ? 16 : 8;
    constexpr int DOUT = (WHICH == 2) ? 4 : 2;
    constexpr int HOUT = (WHICH == 2) ? 8 : 4;
    constexpr int WOUT = (WHICH == 2) ? 8 : 4;
    constexpr int DHW  = DIN * HIN * WIN;
    constexpr int POS  = DOUT * HOUT * WOUT;

    const float* in    = (WHICH == 2) ? g_m1 : g_m2;
    const float* wT    = (WHICH == 2) ? g_wT2 : g_wT3;
    const float* shift = (WHICH == 2) ? g_shift2 : g_shift3;
    float*       out   = (WHICH == 2) ? g_m2 : g_m3;

    __shared__ float As[27][68];
    __shared__ float Bs[27][68];
    __shared__ int   offs[27];

    int pos = blockIdx.x;
    int t = threadIdx.x;
    if (t < 27) {
        int d = pos / (HOUT * WOUT);
        int rem = pos % (HOUT * WOUT);
        int h = rem / WOUT, w = rem % WOUT;
        int kd = t / 9, r = t % 9, kh = r / 3, kw = r % 3;
        int zd = 2 * d - 1 + kd, zh = 2 * h - 1 + kh, zw = 2 * w - 1 + kw;
        bool ok = (unsigned)zd < (unsigned)DIN && (unsigned)zh < (unsigned)HIN &&
                  (unsigned)zw < (unsigned)WIN;
        offs[t] = ok ? ((zd * HIN + zh) * WIN + zw) : -1;
    }
    __syncthreads();

    int b0 = blockIdx.y * 64;
    int o0 = blockIdx.z * 64;
    int tx = t & 15, ty = t >> 4;
    float acc[4][4] = {};

    for (int c = 0; c < CIN; c++) {
        const float* inc = in + (size_t)c * DHW;
        for (int idx = t; idx < 64 * 27; idx += 256) {
            int bb = idx / 27, tap = idx - bb * 27;
            int off = offs[tap];
            As[tap][bb] = (off >= 0)
                ? __ldg(inc + (size_t)(b0 + bb) * (CIN * DHW) + off) : 0.f;
        }
        const float* wc = wT + (size_t)c * 27 * COUT + o0;
        for (int idx = t; idx < 27 * 64; idx += 256) {
            int tap = idx >> 6, oo = idx & 63;
            Bs[tap][oo] = wc[tap * COUT + oo];
        }
        __syncthreads();
#pragma unroll
        for (int tap = 0; tap < 27; tap++) {
            float4 a4 = *(const float4*)&As[tap][ty * 4];
            float4 b4 = *(const float4*)&Bs[tap][tx * 4];
            float a[4] = {a4.x, a4.y, a4.z, a4.w};
            float b[4] = {b4.x, b4.y, b4.z, b4.w};
#pragma unroll
            for (int i = 0; i < 4; i++)
#pragma unroll
                for (int j = 0; j < 4; j++)
                    acc[i][j] = fmaf(a[i], b[j], acc[i][j]);
        }
        __syncthreads();
    }

#pragma unroll
    for (int i = 0; i < 4; i++) {
        int b = b0 + ty * 4 + i;
#pragma unroll
        for (int j = 0; j < 4; j++) {
            int o = o0 + tx * 4 + j;
            float v = fmaxf(acc[i][j] + shift[o], 0.f);
            out[((size_t)b * COUT + o) * POS + pos] = v;
        }
    }
}

// ---------------- gating: pool + fc + softmax ----------------
__global__ void gate_kernel(const float* __restrict__ fc_w, const float* __restrict__ fc_b) {
    int b = blockIdx.x, t = threadIdx.x;  // 128 threads
    __shared__ float pooled[128];
    __shared__ float logit[4];
    const float* p = g_m3 + (size_t)b * 4096 + t * 32;
    float s = 0.f;
#pragma unroll
    for (int i = 0; i < 32; i++) s += p[i];
    pooled[t] = s * (1.0f / 32.0f);
    __syncthreads();
    if (t < 4) {
        float l = fc_b[t];
        const float* wrow = fc_w + t * 128;
        for (int c = 0; c < 128; c++) l = fmaf(pooled[c], wrow[c], l);
        logit[t] = l;
    }
    __syncthreads();
    if (t == 0) {
        float mx = fmaxf(fmaxf(logit[0], logit[1]), fmaxf(logit[2], logit[3]));
        float e0 = expf(logit[0] - mx), e1 = expf(logit[1] - mx);
        float e2 = expf(logit[2] - mx), e3 = expf(logit[3] - mx);
        float inv = 1.f / (e0 + e1 + e2 + e3);
        g_gw[b * 4 + 0] = e0 * inv;
        g_gw[b * 4 + 1] = e1 * inv;
        g_gw[b * 4 + 2] = e2 * inv;
        g_gw[b * 4 + 3] = e3 * inv;
    }
}

// ---------------- GEMM1: GEGLU, hid scaled by gate weight ----------------
// per expert: proj = x @ w1[e] + b1[e]; hid = val * gelu(gate); g_hid[n][e*5120+i] = gw[n][e]*hid
// block tile: 128 rows x 64 paired columns (val + gate), micro 8x8, kT=8
__global__ void geglu_kernel(const float* __restrict__ x, const float* __restrict__ w1,
                             const float* __restrict__ b1) {
    __shared__ float As[8][132];
    __shared__ float Bs[8][132];
    int e = blockIdx.z;
    int m0 = blockIdx.y * 128, n0 = blockIdx.x * 64;
    const float* W = w1 + (size_t)e * 13107200;  // 1280*10240
    int t = threadIdx.x;
    int tx = t & 15, ty = t >> 4;
    int arow = t >> 1, akq = (t & 1) * 4;
    int bk = t >> 5, bnq = (t & 31) * 4;
    int bcol = (bnq < 64) ? (n0 + bnq) : (5120 + n0 + bnq - 64);
    const float* aptr = x + (size_t)(m0 + arow) * 1280 + akq;
    const float* bptr = W + (size_t)bk * 10240 + bcol;

    float acc[8][8];
#pragma unroll
    for (int i = 0; i < 8; i++)
#pragma unroll
        for (int j = 0; j < 8; j++) acc[i][j] = 0.f;

    for (int k0 = 0; k0 < 1280; k0 += 8) {
        float4 av = *(const float4*)(aptr + k0);
        float4 bv = *(const float4*)(bptr + (size_t)k0 * 10240);
        As[akq + 0][arow] = av.x;
        As[akq + 1][arow] = av.y;
        As[akq + 2][arow] = av.z;
        As[akq + 3][arow] = av.w;
        *(float4*)&Bs[bk][bnq] = bv;
        __syncthreads();
#pragma unroll
        for (int k = 0; k < 8; k++) {
            float a[8], b[8];
            *(float4*)(a)     = *(const float4*)&As[k][ty * 4];
            *(float4*)(a + 4) = *(const float4*)&As[k][64 + ty * 4];
            *(float4*)(b)     = *(const float4*)&Bs[k][tx * 4];
            *(float4*)(b + 4) = *(const float4*)&Bs[k][64 + tx * 4];
#pragma unroll
            for (int i = 0; i < 8; i++)
#pragma unroll
                for (int j = 0; j < 8; j++)
                    acc[i][j] = fmaf(a[i], b[j], acc[i][j]);
        }
        __syncthreads();
    }

    const float* b1v = b1 + (size_t)e * 10240 + n0;
#pragma unroll
    for (int i = 0; i < 8; i++) {
        int r = (i < 4) ? (ty * 4 + i) : (64 + ty * 4 + i - 4);
        int n = m0 + r;
        float gwv = g_gw[n * 4 + e];
#pragma unroll
        for (int j = 0; j < 4; j++) {
            int col = tx * 4 + j;
            float v = acc[i][j] + b1v[col];
            float g = acc[i][4 + j] + b1v[5120 + col];
            float hval = v * (0.5f * g * (1.f + erff(g * 0.70710678118654752f)));
            g_hid[(size_t)n * 20480 + e * 5120 + n0 + col] = hval * gwv;
        }
    }
}

// ---------------- GEMM2: out = hid_scaled[1024,20480] @ w2flat[20480,1280] + gated bias
// block tile: 64 rows x 128 cols, micro 8x4, kT=8
__global__ void out_gemm_kernel(const float* __restrict__ w2, const float* __restrict__ b2,
                                float* __restrict__ out) {
    __shared__ float As[8][68];
    __shared__ float Bs[8][132];
    int m0 = blockIdx.y * 64, n0 = blockIdx.x * 128;
    int t = threadIdx.x;
    int tx = t & 31, ty = t >> 5;
    int arow = t >> 1, akq = (t & 1) * 4;
    int bk = t >> 5, bnq = (t & 31) * 4;
    const float* aptr = g_hid + (size_t)(m0 + arow) * 20480 + akq;
    const float* bptr = w2 + (size_t)bk * 1280 + n0 + bnq;

    float acc[8][4];
#pragma unroll
    for (int i = 0; i < 8; i++)
#pragma unroll
        for (int j = 0; j < 4; j++) acc[i][j] = 0.f;

    for (int k0 = 0; k0 < 20480; k0 += 8) {
        if (t < 128) {
            float4 av = *(const float4*)(aptr + k0);
            As[akq + 0][arow] = av.x;
            As[akq + 1][arow] = av.y;
            As[akq + 2][arow] = av.z;
            As[akq + 3][arow] = av.w;
        }
        float4 bv = *(const float4*)(bptr + (size_t)k0 * 1280);
        *(float4*)&Bs[bk][bnq] = bv;
        __syncthreads();
#pragma unroll
        for (int k = 0; k < 8; k++) {
            float a[8], b[4];
            *(float4*)(a)     = *(const float4*)&As[k][ty * 4];
            *(float4*)(a + 4) = *(const float4*)&As[k][32 + ty * 4];
            *(float4*)(b)     = *(const float4*)&Bs[k][tx * 4];
#pragma unroll
            for (int i = 0; i < 8; i++)
#pragma unroll
                for (int j = 0; j < 4; j++)
                    acc[i][j] = fmaf(a[i], b[j], acc[i][j]);
        }
        __syncthreads();
    }

#pragma unroll
    for (int i = 0; i < 8; i++) {
        int n = m0 + ((i < 4) ? (ty * 4 + i) : (32 + ty * 4 + i - 4));
        float gw0 = g_gw[n * 4 + 0], gw1 = g_gw[n * 4 + 1];
        float gw2 = g_gw[n * 4 + 2], gw3 = g_gw[n * 4 + 3];
#pragma unroll
        for (int j = 0; j < 4; j++) {
            int d = n0 + tx * 4 + j;
            float bias = gw0 * b2[d] + gw1 * b2[1280 + d] + gw2 * b2[2560 + d] +
                         gw3 * b2[3840 + d];
            out[(size_t)n * 1280 + d] = acc[i][j] + bias;
        }
    }
}

// ---------------- launch ----------------
extern "C" void kernel_launch(void* const* d_in, const int* in_sizes, int n_in,
                              void* d_out, int out_size) {
    const float* x      = (const float*)d_in[0];
    const float* mask   = (const float*)d_in[1];
    const float* c1w    = (const float*)d_in[2];
    const float* c1b    = (const float*)d_in[3];
    const float* bn1g   = (const float*)d_in[4];
    const float* bn1b   = (const float*)d_in[5];
    const float* bn1m   = (const float*)d_in[6];
    const float* bn1v   = (const float*)d_in[7];
    const float* c2w    = (const float*)d_in[8];
    const float* c2b    = (const float*)d_in[9];
    const float* bn2g   = (const float*)d_in[10];
    const float* bn2b   = (const float*)d_in[11];
    const float* bn2m   = (const float*)d_in[12];
    const float* bn2v   = (const float*)d_in[13];
    const float* c3w    = (const float*)d_in[14];
    const float* c3b    = (const float*)d_in[15];
    const float* bn3g   = (const float*)d_in[16];
    const float* bn3b   = (const float*)d_in[17];
    const float* bn3m   = (const float*)d_in[18];
    const float* bn3v   = (const float*)d_in[19];
    const float* fcw    = (const float*)d_in[20];
    const float* fcb    = (const float*)d_in[21];
    const float* w1     = (const float*)d_in[22];
    const float* b1     = (const float*)d_in[23];
    const float* w2     = (const float*)d_in[24];
    const float* b2     = (const float*)d_in[25];
    float* out = (float*)d_out;

    prep_kernel<2><<<216, 256>>>(c2w, c2b, bn2g, bn2b, bn2m, bn2v);
    prep_kernel<3><<<864, 256>>>(c3w, c3b, bn3g, bn3b, bn3m, bn3v);
    conv1_kernel<<<dim3(1024, 8), 256>>>(mask, c1w, c1b, bn1g, bn1b, bn1m, bn1v);
    conv_gemm_kernel<2><<<dim3(256, 16, 1), 256>>>();
    conv_gemm_kernel<3><<<dim3(32, 16, 2), 256>>>();
    gate_kernel<<<1024, 128>>>(fcw, fcb);
    geglu_kernel<<<dim3(80, 8, 4), 256>>>(x, w1, b1);
    out_gemm_kernel<<<dim3(10, 16), 256>>>(w2, b2, out);
}

// round 6
// speedup vs baseline: 1.6129x; 1.6129x over previous
#include <cuda_runtime.h>
#include <cuda_bf16.h>
#include <math.h>

#define BN_EPS 1e-5f

// ================= scratch =================
__device__ float g_m1[67108864];   // conv1 out [1024][32][8][16][16]
__device__ float g_m2[16777216];   // conv2 out [1024][64][4][8][8]
__device__ float g_m3[4194304];    // conv3 out [1024][128][2][4][4]
__device__ float g_wT2[55296];
__device__ float g_shift2[64];
__device__ float g_wT3[221184];
__device__ float g_shift3[128];
__device__ float g_gw[4096];       // [1024][4]
// bf16 split operands
__device__ __nv_bfloat16 g_xh[1310720],  g_xl[1310720];    // x [1024][1280]
__device__ __nv_bfloat16 g_w1h[52428800], g_w1l[52428800]; // W1^T [40960][1280] (e*10240+j, d)
__device__ __nv_bfloat16 g_w2h[26214400], g_w2l[26214400]; // W2^T [1280][20480] (j, e*5120+i)
__device__ __nv_bfloat16 g_hh[20971520],  g_hl[20971520];  // hid [1024][20480]
__device__ float g_part[5242880];  // [4][1024][1280] split-K partials

// ================= helpers =================
__device__ __forceinline__ unsigned smem_u32(const void* ptr) {
    unsigned a;
    asm("{ .reg .u64 t; cvta.to.shared.u64 t, %1; cvt.u32.u64 %0, t; }" : "=r"(a) : "l"(ptr));
    return a;
}
#define CP_ASYNC16(dst, src) \
    asm volatile("cp.async.cg.shared.global [%0], [%1], 16;" :: "r"(dst), "l"(src))
#define CP_COMMIT() asm volatile("cp.async.commit_group;" ::: "memory")
#define CP_WAIT1()  asm volatile("cp.async.wait_group 1;" ::: "memory")

__device__ __forceinline__ void ldsm4(unsigned* r, unsigned addr) {
    asm volatile("ldmatrix.sync.aligned.m8n8.x4.shared.b16 {%0,%1,%2,%3}, [%4];"
                 : "=r"(r[0]), "=r"(r[1]), "=r"(r[2]), "=r"(r[3]) : "r"(addr));
}
#define MMA16816(c, a, b) \
    asm volatile("mma.sync.aligned.m16n8k16.row.col.f32.bf16.bf16.f32 " \
        "{%0,%1,%2,%3}, {%4,%5,%6,%7}, {%8,%9}, {%0,%1,%2,%3};" \
        : "+f"((c)[0]), "+f"((c)[1]), "+f"((c)[2]), "+f"((c)[3]) \
        : "r"((a)[0]), "r"((a)[1]), "r"((a)[2]), "r"((a)[3]), "r"((b)[0]), "r"((b)[1]))

// ================= prep: conv weights + BN fold =================
template<int WHICH>
__global__ void prep_kernel(const float* __restrict__ w, const float* __restrict__ bias,
                            const float* __restrict__ bng, const float* __restrict__ bnb,
                            const float* __restrict__ bnm, const float* __restrict__ bnv) {
    constexpr int CIN  = (WHICH == 2) ? 32 : 64;
    constexpr int COUT = (WHICH == 2) ? 64 : 128;
    float* wT    = (WHICH == 2) ? g_wT2 : g_wT3;
    float* shift = (WHICH == 2) ? g_shift2 : g_shift3;
    int idx = blockIdx.x * 256 + threadIdx.x;
    const int total = CIN * 27 * COUT;
    if (idx < total) {
        int o = idx % COUT;
        int r = idx / COUT;
        int tap = r % 27;
        int c = r / 27;
        float s = rsqrtf(bnv[o] + BN_EPS) * bng[o];
        wT[idx] = w[((size_t)o * CIN + c) * 27 + tap] * s;
    }
    if (idx < COUT) {
        float s = rsqrtf(bnv[idx] + BN_EPS) * bng[idx];
        shift[idx] = (bias[idx] - bnm[idx]) * s + bnb[idx];
    }
}

// ================= bf16-split conversion =================
__global__ void cvt_x_kernel(const float* __restrict__ x) {
    int i = blockIdx.x * 256 + threadIdx.x;
    if (i < 1310720) {
        float v = x[i];
        __nv_bfloat16 h = __float2bfloat16_rn(v);
        g_xh[i] = h;
        g_xl[i] = __float2bfloat16_rn(v - __bfloat162float(h));
    }
}

// w1 [4][1280][10240] -> Wt1 [(e*10240+j)][1280]
__global__ void trans_w1_kernel(const float* __restrict__ w1) {
    __shared__ float tile[32][33];
    int e = blockIdx.z;
    int j0 = blockIdx.x * 32, d0 = blockIdx.y * 32;
    const float* W = w1 + (size_t)e * 13107200;
    int tx = threadIdx.x, ty = threadIdx.y;
#pragma unroll
    for (int r = 0; r < 32; r += 8)
        tile[ty + r][tx] = W[(size_t)(d0 + ty + r) * 10240 + j0 + tx];
    __syncthreads();
#pragma unroll
    for (int r = 0; r < 32; r += 8) {
        float v = tile[tx][ty + r];
        size_t o = (size_t)(e * 10240 + j0 + ty + r) * 1280 + d0 + tx;
        __nv_bfloat16 h = __float2bfloat16_rn(v);
        g_w1h[o] = h;
        g_w1l[o] = __float2bfloat16_rn(v - __bfloat162float(h));
    }
}

// w2 [4][5120][1280] -> Wt2 [j][e*5120+i]  (1280 x 20480)
__global__ void trans_w2_kernel(const float* __restrict__ w2) {
    __shared__ float tile[32][33];
    int e = blockIdx.z;
    int j0 = blockIdx.x * 32, i0 = blockIdx.y * 32;
    const float* W = w2 + (size_t)e * 6553600;
    int tx = threadIdx.x, ty = threadIdx.y;
#pragma unroll
    for (int r = 0; r < 32; r += 8)
        tile[ty + r][tx] = W[(size_t)(i0 + ty + r) * 1280 + j0 + tx];
    __syncthreads();
#pragma unroll
    for (int r = 0; r < 32; r += 8) {
        float v = tile[tx][ty + r];
        size_t o = (size_t)(j0 + ty + r) * 20480 + e * 5120 + i0 + tx;
        __nv_bfloat16 h = __float2bfloat16_rn(v);
        g_w2h[o] = h;
        g_w2l[o] = __float2bfloat16_rn(v - __bfloat162float(h));
    }
}

// ================= conv1 =================
__global__ void conv1_kernel(const float* __restrict__ mask,
                             const float* __restrict__ w, const float* __restrict__ bias,
                             const float* __restrict__ bng, const float* __restrict__ bnb,
                             const float* __restrict__ bnm, const float* __restrict__ bnv) {
    __shared__ float ws[32][27];
    __shared__ float sscale[32], sshift[32];
    int t = threadIdx.x;
    if (t < 32) {
        float s = rsqrtf(bnv[t] + BN_EPS) * bng[t];
        sscale[t] = s;
        sshift[t] = (bias[t] - bnm[t]) * s + bnb[t];
    }
    __syncthreads();
    for (int idx = t; idx < 864; idx += 256) {
        int o = idx / 27, tap = idx % 27;
        ws[o][tap] = w[idx] * sscale[o];
    }
    __syncthreads();

    int b = blockIdx.x, d = blockIdx.y;
    int h = t >> 4, wq = t & 15;
    const float* mb = mask + (size_t)b * 16384;

    float v[27];
#pragma unroll
    for (int kd = 0; kd < 3; kd++)
#pragma unroll
        for (int kh = 0; kh < 3; kh++)
#pragma unroll
            for (int kw = 0; kw < 3; kw++) {
                int zd = 2 * d - 1 + kd, zh = 2 * h - 1 + kh, zw = 2 * wq - 1 + kw;
                bool ok = (unsigned)zd < 16u && (unsigned)zh < 32u && (unsigned)zw < 32u;
                v[(kd * 3 + kh) * 3 + kw] = ok ? mb[zd * 1024 + zh * 32 + zw] : 0.f;
            }

    size_t outbase = (size_t)b * 65536 + (size_t)d * 256 + h * 16 + wq;
#pragma unroll
    for (int o = 0; o < 32; o++) {
        float acc = 0.f;
#pragma unroll
        for (int tap = 0; tap < 27; tap++) acc = fmaf(ws[o][tap], v[tap], acc);
        acc += sshift[o];
        g_m1[outbase + (size_t)o * 2048] = fmaxf(acc, 0.f);
    }
}

// ================= conv2/3 implicit GEMM =================
template<int WHICH>
__global__ void conv_gemm_kernel() {
    constexpr int CIN  = (WHICH == 2) ? 32 : 64;
    constexpr int COUT = (WHICH == 2) ? 64 : 128;
    constexpr int DIN  = (WHICH == 2) ? 8 : 4;
    constexpr int HIN  = (WHICH == 2) ? 16 : 8;
    constexpr int WIN  = (WHICH == 2) ? 16 : 8;
    constexpr int HOUT = (WHICH == 2) ? 8 : 4;
    constexpr int WOUT = (WHICH == 2) ? 8 : 4;
    constexpr int DHW  = DIN * HIN * WIN;
    constexpr int POS  = ((WHICH == 2) ? 4 : 2) * HOUT * WOUT;

    const float* in    = (WHICH == 2) ? g_m1 : g_m2;
    const float* wT    = (WHICH == 2) ? g_wT2 : g_wT3;
    const float* shift = (WHICH == 2) ? g_shift2 : g_shift3;
    float*       out   = (WHICH == 2) ? g_m2 : g_m3;

    __shared__ float As[27][68];
    __shared__ float Bs[27][68];
    __shared__ int   offs[27];

    int pos = blockIdx.x;
    int t = threadIdx.x;
    if (t < 27) {
        int d = pos / (HOUT * WOUT);
        int rem = pos % (HOUT * WOUT);
        int h = rem / WOUT, w = rem % WOUT;
        int kd = t / 9, r = t % 9, kh = r / 3, kw = r % 3;
        int zd = 2 * d - 1 + kd, zh = 2 * h - 1 + kh, zw = 2 * w - 1 + kw;
        bool ok = (unsigned)zd < (unsigned)DIN && (unsigned)zh < (unsigned)HIN &&
                  (unsigned)zw < (unsigned)WIN;
        offs[t] = ok ? ((zd * HIN + zh) * WIN + zw) : -1;
    }
    __syncthreads();

    int b0 = blockIdx.y * 64;
    int o0 = blockIdx.z * 64;
    int tx = t & 15, ty = t >> 4;
    float acc[4][4] = {};

    for (int c = 0; c < CIN; c++) {
        const float* inc = in + (size_t)c * DHW;
        for (int idx = t; idx < 64 * 27; idx += 256) {
            int bb = idx / 27, tap = idx - bb * 27;
            int off = offs[tap];
            As[tap][bb] = (off >= 0)
                ? __ldg(inc + (size_t)(b0 + bb) * (CIN * DHW) + off) : 0.f;
        }
        const float* wc = wT + (size_t)c * 27 * COUT + o0;
        for (int idx = t; idx < 27 * 64; idx += 256) {
            int tap = idx >> 6, oo = idx & 63;
            Bs[tap][oo] = wc[tap * COUT + oo];
        }
        __syncthreads();
#pragma unroll
        for (int tap = 0; tap < 27; tap++) {
            float4 a4 = *(const float4*)&As[tap][ty * 4];
            float4 b4 = *(const float4*)&Bs[tap][tx * 4];
            float a[4] = {a4.x, a4.y, a4.z, a4.w};
            float b[4] = {b4.x, b4.y, b4.z, b4.w};
#pragma unroll
            for (int i = 0; i < 4; i++)
#pragma unroll
                for (int j = 0; j < 4; j++)
                    acc[i][j] = fmaf(a[i], b[j], acc[i][j]);
        }
        __syncthreads();
    }

#pragma unroll
    for (int i = 0; i < 4; i++) {
        int b = b0 + ty * 4 + i;
#pragma unroll
        for (int j = 0; j < 4; j++) {
            int o = o0 + tx * 4 + j;
            float v = fmaxf(acc[i][j] + shift[o], 0.f);
            out[((size_t)b * COUT + o) * POS + pos] = v;
        }
    }
}

// ================= gate =================
__global__ void gate_kernel(const float* __restrict__ fc_w, const float* __restrict__ fc_b) {
    int b = blockIdx.x, t = threadIdx.x;
    __shared__ float pooled[128];
    __shared__ float logit[4];
    const float* p = g_m3 + (size_t)b * 4096 + t * 32;
    float s = 0.f;
#pragma unroll
    for (int i = 0; i < 32; i++) s += p[i];
    pooled[t] = s * (1.0f / 32.0f);
    __syncthreads();
    if (t < 4) {
        float l = fc_b[t];
        const float* wrow = fc_w + t * 128;
        for (int c = 0; c < 128; c++) l = fmaf(pooled[c], wrow[c], l);
        logit[t] = l;
    }
    __syncthreads();
    if (t == 0) {
        float mx = fmaxf(fmaxf(logit[0], logit[1]), fmaxf(logit[2], logit[3]));
        float e0 = expf(logit[0] - mx), e1 = expf(logit[1] - mx);
        float e2 = expf(logit[2] - mx), e3 = expf(logit[3] - mx);
        float inv = 1.f / (e0 + e1 + e2 + e3);
        g_gw[b * 4 + 0] = e0 * inv;
        g_gw[b * 4 + 1] = e1 * inv;
        g_gw[b * 4 + 2] = e2 * inv;
        g_gw[b * 4 + 3] = e3 * inv;
    }
}

// ================= mma.sync GEMM (MODE 1 = GEGLU, MODE 2 = output/split-K) =================
// CTA tile 128x128, kT=32, 8 warps (4Mx2N), warp tile 32x64.
// 3-pass split-bf16: AH*BH + AH*BL + AL*BH, fp32 accumulate.
// smem per stage: 4 tiles of [128 rows][40 halves] (80B padded rows) = 40960 B; 2 stages.
#define TILE_B   10240
#define STAGE_B  40960
#define SMEM_BYTES 81920

template<int MODE>
__global__ void __launch_bounds__(256, 1) mma_gemm_kernel(const float* __restrict__ b1) {
    extern __shared__ char smem[];
    unsigned sb = smem_u32(smem);
    int t = threadIdx.x, wid = t >> 5, lid = t & 31;

    constexpr int KT = (MODE == 1) ? 40 : 160;

    int m0 = blockIdx.x * 128;
    int e = 0, h0 = 0, n0 = 0;
    size_t kbase = 0;
    if (MODE == 1) { e = blockIdx.y / 80; h0 = (blockIdx.y % 80) * 64; }
    else           { n0 = blockIdx.y * 128; kbase = (size_t)blockIdx.z * 5120; }

    // per-thread cp.async slots: 2048 16B-chunks / 256 threads = 8 each
    const __nv_bfloat16* gsrc[8];
    unsigned sdst[8];
#pragma unroll
    for (int i = 0; i < 8; i++) {
        int c = t + 256 * i;
        int tile = c >> 9, rs = c & 511, row = rs >> 2, seg = rs & 3;
        const __nv_bfloat16* base;
        size_t grow;
        if (MODE == 1) {
            if (tile < 2) {
                base = tile ? g_xl : g_xh;
                grow = (size_t)(m0 + row) * 1280;
            } else {
                int g = e * 10240 + (row & 1) * 5120 + h0 + (row >> 1);
                base = (tile == 2) ? g_w1h : g_w1l;
                grow = (size_t)g * 1280;
            }
        } else {
            if (tile < 2) {
                base = tile ? g_hl : g_hh;
                grow = (size_t)(m0 + row) * 20480;
            } else {
                base = (tile == 2) ? g_w2h : g_w2l;
                grow = (size_t)(n0 + row) * 20480;
            }
        }
        gsrc[i] = base + grow + seg * 8;
        sdst[i] = sb + tile * TILE_B + row * 80 + seg * 16;
    }

    // prologue: stages 0,1
#pragma unroll
    for (int st = 0; st < 2; st++) {
        size_t k0 = kbase + st * 32;
#pragma unroll
        for (int i = 0; i < 8; i++) CP_ASYNC16(sdst[i] + st * STAGE_B, gsrc[i] + k0);
        CP_COMMIT();
    }

    float cacc[2][8][4];
#pragma unroll
    for (int mf = 0; mf < 2; mf++)
#pragma unroll
        for (int nf = 0; nf < 8; nf++)
#pragma unroll
            for (int q = 0; q < 4; q++) cacc[mf][nf][q] = 0.f;

    unsigned warpM = (wid & 3) * 32;
    unsigned warpN = (wid >> 2) * 64;

    for (int kt = 0; kt < KT; kt++) {
        CP_WAIT1();
        __syncthreads();
        int st = kt & 1;
        unsigned sA_H = sb + st * STAGE_B;
        unsigned sA_L = sA_H + TILE_B;
        unsigned sB_H = sA_H + 2 * TILE_B;
        unsigned sB_L = sA_H + 3 * TILE_B;

#pragma unroll
        for (int ks = 0; ks < 2; ks++) {
            unsigned aH[2][4], aL[2][4];
#pragma unroll
            for (int mf = 0; mf < 2; mf++) {
                unsigned off = (warpM + mf * 16 + (lid & 15)) * 80 + ks * 32 + (lid >> 4) * 16;
                ldsm4(aH[mf], sA_H + off);
                ldsm4(aL[mf], sA_L + off);
            }
            unsigned bH[8][2], bL[8][2];
#pragma unroll
            for (int nf2 = 0; nf2 < 4; nf2++) {
                unsigned off = (warpN + nf2 * 16 + (lid & 7) + ((lid >> 4) & 1) * 8) * 80 +
                               ks * 32 + ((lid >> 3) & 1) * 16;
                unsigned r[4];
                ldsm4(r, sB_H + off);
                bH[2 * nf2][0] = r[0]; bH[2 * nf2][1] = r[1];
                bH[2 * nf2 + 1][0] = r[2]; bH[2 * nf2 + 1][1] = r[3];
                ldsm4(r, sB_L + off);
                bL[2 * nf2][0] = r[0]; bL[2 * nf2][1] = r[1];
                bL[2 * nf2 + 1][0] = r[2]; bL[2 * nf2 + 1][1] = r[3];
            }
#pragma unroll
            for (int mf = 0; mf < 2; mf++)
#pragma unroll
                for (int nf = 0; nf < 8; nf++) {
                    MMA16816(cacc[mf][nf], aH[mf], bH[nf]);
                    MMA16816(cacc[mf][nf], aH[mf], bL[nf]);
                    MMA16816(cacc[mf][nf], aL[mf], bH[nf]);
                }
        }
        __syncthreads();
        int ktn = kt + 2;
        if (ktn < KT) {
            size_t k0 = kbase + (size_t)ktn * 32;
#pragma unroll
            for (int i = 0; i < 8; i++) CP_ASYNC16(sdst[i] + st * STAGE_B, gsrc[i] + k0);
        }
        CP_COMMIT();
    }

    // epilogue
    int grp = lid >> 2, qd = lid & 3;
    if (MODE == 1) {
        const float* bv = b1 + (size_t)e * 10240;
#pragma unroll
        for (int mf = 0; mf < 2; mf++) {
#pragma unroll
            for (int half = 0; half < 2; half++) {
                int n = m0 + warpM + mf * 16 + grp + half * 8;
                float gw = g_gw[n * 4 + e];
                size_t ob = (size_t)n * 20480 + (size_t)e * 5120;
#pragma unroll
                for (int nf = 0; nf < 8; nf++) {
                    int h = h0 + (warpN >> 1) + nf * 4 + qd;
                    float val  = cacc[mf][nf][half * 2 + 0];
                    float gate = cacc[mf][nf][half * 2 + 1];
                    float v = val + bv[h];
                    float g = gate + bv[5120 + h];
                    float hid = v * (0.5f * g * (1.f + erff(g * 0.70710678118654752f))) * gw;
                    __nv_bfloat16 hh = __float2bfloat16_rn(hid);
                    g_hh[ob + h] = hh;
                    g_hl[ob + h] = __float2bfloat16_rn(hid - __bfloat162float(hh));
                }
            }
        }
    } else {
        size_t zb = (size_t)blockIdx.z * 1310720;
#pragma unroll
        for (int mf = 0; mf < 2; mf++) {
#pragma unroll
            for (int half = 0; half < 2; half++) {
                int n = m0 + warpM + mf * 16 + grp + half * 8;
                size_t rb = zb + (size_t)n * 1280;
#pragma unroll
                for (int nf = 0; nf < 8; nf++) {
                    int col = n0 + warpN + nf * 8 + qd * 2;
                    g_part[rb + col]     = cacc[mf][nf][half * 2 + 0];
                    g_part[rb + col + 1] = cacc[mf][nf][half * 2 + 1];
                }
            }
        }
    }
}

// ================= split-K reduce + gated bias =================
__global__ void reduce_kernel(const float* __restrict__ b2, float* __restrict__ out) {
    int i = blockIdx.x * 256 + threadIdx.x;  // 1310720 outputs
    int n = i / 1280, j = i - n * 1280;
    float s = g_part[i] + g_part[1310720 + i] + g_part[2621440 + i] + g_part[3932160 + i];
    const float* gw = g_gw + n * 4;
    s += gw[0] * b2[j] + gw[1] * b2[1280 + j] + gw[2] * b2[2560 + j] + gw[3] * b2[3840 + j];
    out[i] = s;
}

// ================= launch =================
extern "C" void kernel_launch(void* const* d_in, const int* in_sizes, int n_in,
                              void* d_out, int out_size) {
    const float* x    = (const float*)d_in[0];
    const float* mask = (const float*)d_in[1];
    const float* c1w  = (const float*)d_in[2];
    const float* c1b  = (const float*)d_in[3];
    const float* bn1g = (const float*)d_in[4];
    const float* bn1b = (const float*)d_in[5];
    const float* bn1m = (const float*)d_in[6];
    const float* bn1v = (const float*)d_in[7];
    const float* c2w  = (const float*)d_in[8];
    const float* c2b  = (const float*)d_in[9];
    const float* bn2g = (const float*)d_in[10];
    const float* bn2b = (const float*)d_in[11];
    const float* bn2m = (const float*)d_in[12];
    const float* bn2v = (const float*)d_in[13];
    const float* c3w  = (const float*)d_in[14];
    const float* c3b  = (const float*)d_in[15];
    const float* bn3g = (const float*)d_in[16];
    const float* bn3b = (const float*)d_in[17];
    const float* bn3m = (const float*)d_in[18];
    const float* bn3v = (const float*)d_in[19];
    const float* fcw  = (const float*)d_in[20];
    const float* fcb  = (const float*)d_in[21];
    const float* w1   = (const float*)d_in[22];
    const float* b1   = (const float*)d_in[23];
    const float* w2   = (const float*)d_in[24];
    const float* b2   = (const float*)d_in[25];
    float* out = (float*)d_out;

    cudaFuncSetAttribute(mma_gemm_kernel<1>, cudaFuncAttributeMaxDynamicSharedMemorySize, SMEM_BYTES);
    cudaFuncSetAttribute(mma_gemm_kernel<2>, cudaFuncAttributeMaxDynamicSharedMemorySize, SMEM_BYTES);

    prep_kernel<2><<<216, 256>>>(c2w, c2b, bn2g, bn2b, bn2m, bn2v);
    prep_kernel<3><<<864, 256>>>(c3w, c3b, bn3g, bn3b, bn3m, bn3v);
    cvt_x_kernel<<<5120, 256>>>(x);
    trans_w1_kernel<<<dim3(320, 40, 4), dim3(32, 8)>>>(w1);
    trans_w2_kernel<<<dim3(40, 160, 4), dim3(32, 8)>>>(w2);
    conv1_kernel<<<dim3(1024, 8), 256>>>(mask, c1w, c1b, bn1g, bn1b, bn1m, bn1v);
    conv_gemm_kernel<2><<<dim3(256, 16, 1), 256>>>();
    conv_gemm_kernel<3><<<dim3(32, 16, 2), 256>>>();
    gate_kernel<<<1024, 128>>>(fcw, fcb);
    mma_gemm_kernel<1><<<dim3(8, 320), 256, SMEM_BYTES>>>(b1);
    mma_gemm_kernel<2><<<dim3(8, 10, 4), 256, SMEM_BYTES>>>(b1);
    reduce_kernel<<<5120, 256>>>(b2, out);
}

// round 7
// speedup vs baseline: 2.5230x; 1.5643x over previous
#include <cuda_runtime.h>
#include <cuda_bf16.h>
#include <math.h>

#define BN_EPS 1e-5f

// ================= scratch =================
__device__ float g_m1[67108864];   // conv1 out, channels-last [1024][8][16][16][32]
__device__ float g_m2[16777216];   // conv2 out, channels-last [1024][256][64]
__device__ float g_m3[4194304];    // conv3 out, channels-last [1024][32][128]
__device__ float g_wT2[55296];     // [tap27][c32][o64]
__device__ float g_shift2[64];
__device__ float g_wT3[221184];    // [tap27][c64][o128]
__device__ float g_shift3[128];
__device__ float g_gw[4096];       // [1024][4]
// bf16 split operands
__device__ __nv_bfloat16 g_xh[1310720],  g_xl[1310720];    // x [1024][1280]
__device__ __nv_bfloat16 g_w1h[52428800], g_w1l[52428800]; // W1^T [40960][1280]
__device__ __nv_bfloat16 g_w2h[26214400], g_w2l[26214400]; // W2^T [1280][20480]
__device__ __nv_bfloat16 g_hh[20971520],  g_hl[20971520];  // hid [1024][20480]
__device__ float g_part[5242880];  // [4][1024][1280] split-K partials

// ================= helpers =================
__device__ __forceinline__ unsigned smem_u32(const void* ptr) {
    unsigned a;
    asm("{ .reg .u64 t; cvta.to.shared.u64 t, %1; cvt.u32.u64 %0, t; }" : "=r"(a) : "l"(ptr));
    return a;
}
#define CP_ASYNC16(dst, src) \
    asm volatile("cp.async.cg.shared.global [%0], [%1], 16;" :: "r"(dst), "l"(src))
#define CP_COMMIT() asm volatile("cp.async.commit_group;" ::: "memory")
#define CP_WAIT1()  asm volatile("cp.async.wait_group 1;" ::: "memory")

__device__ __forceinline__ void ldsm4(unsigned* r, unsigned addr) {
    asm volatile("ldmatrix.sync.aligned.m8n8.x4.shared.b16 {%0,%1,%2,%3}, [%4];"
                 : "=r"(r[0]), "=r"(r[1]), "=r"(r[2]), "=r"(r[3]) : "r"(addr));
}
#define MMA16816(c, a, b0v, b1v) \
    asm volatile("mma.sync.aligned.m16n8k16.row.col.f32.bf16.bf16.f32 " \
        "{%0,%1,%2,%3}, {%4,%5,%6,%7}, {%8,%9}, {%0,%1,%2,%3};" \
        : "+f"((c)[0]), "+f"((c)[1]), "+f"((c)[2]), "+f"((c)[3]) \
        : "r"((a)[0]), "r"((a)[1]), "r"((a)[2]), "r"((a)[3]), "r"(b0v), "r"(b1v))

// ================= prep: conv weights + BN fold -> [tap][c][o] =================
template<int WHICH>
__global__ void prep_kernel(const float* __restrict__ w, const float* __restrict__ bias,
                            const float* __restrict__ bng, const float* __restrict__ bnb,
                            const float* __restrict__ bnm, const float* __restrict__ bnv) {
    constexpr int CIN  = (WHICH == 2) ? 32 : 64;
    constexpr int COUT = (WHICH == 2) ? 64 : 128;
    float* wT    = (WHICH == 2) ? g_wT2 : g_wT3;
    float* shift = (WHICH == 2) ? g_shift2 : g_shift3;
    int idx = blockIdx.x * 256 + threadIdx.x;
    const int total = CIN * 27 * COUT;
    if (idx < total) {
        int o = idx % COUT;
        int r = idx / COUT;
        int c = r % CIN;
        int tap = r / CIN;
        float s = rsqrtf(bnv[o] + BN_EPS) * bng[o];
        wT[idx] = w[((size_t)o * CIN + c) * 27 + tap] * s;
    }
    if (idx < COUT) {
        float s = rsqrtf(bnv[idx] + BN_EPS) * bng[idx];
        shift[idx] = (bias[idx] - bnm[idx]) * s + bnb[idx];
    }
}

// ================= bf16-split conversion =================
__global__ void cvt_x_kernel(const float* __restrict__ x) {
    int i = blockIdx.x * 256 + threadIdx.x;
    if (i < 1310720) {
        float v = x[i];
        __nv_bfloat16 h = __float2bfloat16_rn(v);
        g_xh[i] = h;
        g_xl[i] = __float2bfloat16_rn(v - __bfloat162float(h));
    }
}

__global__ void trans_w1_kernel(const float* __restrict__ w1) {
    __shared__ float tile[32][33];
    int e = blockIdx.z;
    int j0 = blockIdx.x * 32, d0 = blockIdx.y * 32;
    const float* W = w1 + (size_t)e * 13107200;
    int tx = threadIdx.x, ty = threadIdx.y;
#pragma unroll
    for (int r = 0; r < 32; r += 8)
        tile[ty + r][tx] = W[(size_t)(d0 + ty + r) * 10240 + j0 + tx];
    __syncthreads();
#pragma unroll
    for (int r = 0; r < 32; r += 8) {
        float v = tile[tx][ty + r];
        size_t o = (size_t)(e * 10240 + j0 + ty + r) * 1280 + d0 + tx;
        __nv_bfloat16 h = __float2bfloat16_rn(v);
        g_w1h[o] = h;
        g_w1l[o] = __float2bfloat16_rn(v - __bfloat162float(h));
    }
}

__global__ void trans_w2_kernel(const float* __restrict__ w2) {
    __shared__ float tile[32][33];
    int e = blockIdx.z;
    int j0 = blockIdx.x * 32, i0 = blockIdx.y * 32;
    const float* W = w2 + (size_t)e * 6553600;
    int tx = threadIdx.x, ty = threadIdx.y;
#pragma unroll
    for (int r = 0; r < 32; r += 8)
        tile[ty + r][tx] = W[(size_t)(i0 + ty + r) * 1280 + j0 + tx];
    __syncthreads();
#pragma unroll
    for (int r = 0; r < 32; r += 8) {
        float v = tile[tx][ty + r];
        size_t o = (size_t)(j0 + ty + r) * 20480 + e * 5120 + i0 + tx;
        __nv_bfloat16 h = __float2bfloat16_rn(v);
        g_w2h[o] = h;
        g_w2l[o] = __float2bfloat16_rn(v - __bfloat162float(h));
    }
}

// ================= conv1: channels-last output =================
__global__ void conv1_kernel(const float* __restrict__ mask,
                             const float* __restrict__ w, const float* __restrict__ bias,
                             const float* __restrict__ bng, const float* __restrict__ bnb,
                             const float* __restrict__ bnm, const float* __restrict__ bnv) {
    __shared__ float ws[32][27];
    __shared__ float sscale[32], sshift[32];
    int t = threadIdx.x;
    if (t < 32) {
        float s = rsqrtf(bnv[t] + BN_EPS) * bng[t];
        sscale[t] = s;
        sshift[t] = (bias[t] - bnm[t]) * s + bnb[t];
    }
    __syncthreads();
    for (int idx = t; idx < 864; idx += 256) {
        int o = idx / 27, tap = idx % 27;
        ws[o][tap] = w[idx] * sscale[o];
    }
    __syncthreads();

    int b = blockIdx.x, d = blockIdx.y;
    int h = t >> 4, wq = t & 15;
    const float* mb = mask + (size_t)b * 16384;

    float v[27];
#pragma unroll
    for (int kd = 0; kd < 3; kd++)
#pragma unroll
        for (int kh = 0; kh < 3; kh++)
#pragma unroll
            for (int kw = 0; kw < 3; kw++) {
                int zd = 2 * d - 1 + kd, zh = 2 * h - 1 + kh, zw = 2 * wq - 1 + kw;
                bool ok = (unsigned)zd < 16u && (unsigned)zh < 32u && (unsigned)zw < 32u;
                v[(kd * 3 + kh) * 3 + kw] = ok ? mb[zd * 1024 + zh * 32 + zw] : 0.f;
            }

    float o32[32];
#pragma unroll
    for (int o = 0; o < 32; o++) {
        float acc = 0.f;
#pragma unroll
        for (int tap = 0; tap < 27; tap++) acc = fmaf(ws[o][tap], v[tap], acc);
        o32[o] = fmaxf(acc + sshift[o], 0.f);
    }
    float* op = g_m1 + ((((size_t)b * 8 + d) * 256) + t) * 32;
#pragma unroll
    for (int q = 0; q < 8; q++)
        *(float4*)(op + q * 4) = make_float4(o32[q * 4], o32[q * 4 + 1],
                                             o32[q * 4 + 2], o32[q * 4 + 3]);
}

// ================= conv2/3 channels-last implicit GEMM =================
// out[(b*POS+pos)*COUT+o] = relu(sum_{tap,c} in[(b*DHW+off(pos,tap))*CIN+c] * wT[tap][c][o] + shift)
template<int WHICH>
__global__ void conv_gemm_kernel() {
    constexpr int CIN  = (WHICH == 2) ? 32 : 64;
    constexpr int COUT = (WHICH == 2) ? 64 : 128;
    constexpr int DIN  = (WHICH == 2) ? 8 : 4;
    constexpr int HIN  = (WHICH == 2) ? 16 : 8;
    constexpr int WIN  = (WHICH == 2) ? 16 : 8;
    constexpr int HOUT = (WHICH == 2) ? 8 : 4;
    constexpr int WOUT = (WHICH == 2) ? 8 : 4;
    constexpr int DHW  = DIN * HIN * WIN;
    constexpr int POS  = ((WHICH == 2) ? 4 : 2) * HOUT * WOUT;
    constexpr int CINQ = CIN / 4;

    const float* in    = (WHICH == 2) ? g_m1 : g_m2;
    const float* wT    = (WHICH == 2) ? g_wT2 : g_wT3;
    const float* shift = (WHICH == 2) ? g_shift2 : g_shift3;
    float*       out   = (WHICH == 2) ? g_m2 : g_m3;

    __shared__ float As[CIN][68];
    __shared__ float Bs[CIN][68];
    __shared__ int   offs[27];

    int pos = blockIdx.x;
    int t = threadIdx.x;
    if (t < 27) {
        int d = pos / (HOUT * WOUT);
        int rem = pos % (HOUT * WOUT);
        int h = rem / WOUT, w = rem % WOUT;
        int kd = t / 9, r = t % 9, kh = r / 3, kw = r % 3;
        int zd = 2 * d - 1 + kd, zh = 2 * h - 1 + kh, zw = 2 * w - 1 + kw;
        bool ok = (unsigned)zd < (unsigned)DIN && (unsigned)zh < (unsigned)HIN &&
                  (unsigned)zw < (unsigned)WIN;
        offs[t] = ok ? ((zd * HIN + zh) * WIN + zw) : -1;
    }
    __syncthreads();

    int b0 = blockIdx.y * 64;
    int o0 = blockIdx.z * 64;
    int tx = t & 15, ty = t >> 4;
    float acc[4][4] = {};

    for (int tap = 0; tap < 27; tap++) {
        int off = offs[tap];
        if (off < 0) continue;
        __syncthreads();
        // A: 64 rows x CIN channels, contiguous per row
        const float* ibase = in + (size_t)off * CIN;
#pragma unroll
        for (int i = 0; i < CINQ / 4; i++) {  // conv2: 2, conv3: 4 float4 per thread
            int idx = t + 256 * i;
            int bb = idx / CINQ, c4 = idx % CINQ;
            float4 v = *(const float4*)(ibase + (size_t)(b0 + bb) * (DHW * CIN) + c4 * 4);
            As[c4 * 4 + 0][bb] = v.x;
            As[c4 * 4 + 1][bb] = v.y;
            As[c4 * 4 + 2][bb] = v.z;
            As[c4 * 4 + 3][bb] = v.w;
        }
        // B: CIN rows x 64 outch
        const float* wb = wT + (size_t)tap * CIN * COUT + o0;
#pragma unroll
        for (int i = 0; i < CINQ / 4; i++) {
            int idx = t + 256 * i;
            int c = idx / 16, o4 = idx % 16;
            *(float4*)&Bs[c][o4 * 4] = *(const float4*)(wb + (size_t)c * COUT + o4 * 4);
        }
        __syncthreads();
#pragma unroll
        for (int k = 0; k < CIN; k++) {
            float4 a4 = *(const float4*)&As[k][ty * 4];
            float4 b4 = *(const float4*)&Bs[k][tx * 4];
            float a[4] = {a4.x, a4.y, a4.z, a4.w};
            float b[4] = {b4.x, b4.y, b4.z, b4.w};
#pragma unroll
            for (int i = 0; i < 4; i++)
#pragma unroll
                for (int j = 0; j < 4; j++)
                    acc[i][j] = fmaf(a[i], b[j], acc[i][j]);
        }
    }

#pragma unroll
    for (int i = 0; i < 4; i++) {
        int b = b0 + ty * 4 + i;
        float* op = out + ((size_t)b * POS + pos) * COUT + o0 + tx * 4;
        float4 v;
        v.x = fmaxf(acc[i][0] + shift[o0 + tx * 4 + 0], 0.f);
        v.y = fmaxf(acc[i][1] + shift[o0 + tx * 4 + 1], 0.f);
        v.z = fmaxf(acc[i][2] + shift[o0 + tx * 4 + 2], 0.f);
        v.w = fmaxf(acc[i][3] + shift[o0 + tx * 4 + 3], 0.f);
        *(float4*)op = v;
    }
}

// ================= gate =================
__global__ void gate_kernel(const float* __restrict__ fc_w, const float* __restrict__ fc_b) {
    int b = blockIdx.x, t = threadIdx.x;  // 128 threads, t = channel
    __shared__ float pooled[128];
    __shared__ float logit[4];
    const float* p = g_m3 + (size_t)b * 4096 + t;
    float s = 0.f;
#pragma unroll
    for (int i = 0; i < 32; i++) s += p[i * 128];
    pooled[t] = s * (1.0f / 32.0f);
    __syncthreads();
    if (t < 4) {
        float l = fc_b[t];
        const float* wrow = fc_w + t * 128;
        for (int c = 0; c < 128; c++) l = fmaf(pooled[c], wrow[c], l);
        logit[t] = l;
    }
    __syncthreads();
    if (t == 0) {
        float mx = fmaxf(fmaxf(logit[0], logit[1]), fmaxf(logit[2], logit[3]));
        float e0 = expf(logit[0] - mx), e1 = expf(logit[1] - mx);
        float e2 = expf(logit[2] - mx), e3 = expf(logit[3] - mx);
        float inv = 1.f / (e0 + e1 + e2 + e3);
        g_gw[b * 4 + 0] = e0 * inv;
        g_gw[b * 4 + 1] = e1 * inv;
        g_gw[b * 4 + 2] = e2 * inv;
        g_gw[b * 4 + 3] = e3 * inv;
    }
}

// ================= mma.sync GEMM (MODE 1 = GEGLU, MODE 2 = output/split-K) =================
#define TILE_B   10240
#define STAGE_B  40960
#define SMEM_BYTES 81920

template<int MODE>
__global__ void __launch_bounds__(256, 2) mma_gemm_kernel(const float* __restrict__ b1) {
    extern __shared__ char smem[];
    unsigned sb = smem_u32(smem);
    int t = threadIdx.x, wid = t >> 5, lid = t & 31;

    constexpr int KT = (MODE == 1) ? 40 : 160;

    int m0 = blockIdx.x * 128;
    int e = 0, h0 = 0, n0 = 0;
    size_t kbase = 0;
    if (MODE == 1) { e = blockIdx.y / 80; h0 = (blockIdx.y % 80) * 64; }
    else           { n0 = blockIdx.y * 128; kbase = (size_t)blockIdx.z * 5120; }

    const __nv_bfloat16* gsrc[8];
    unsigned sdst[8];
#pragma unroll
    for (int i = 0; i < 8; i++) {
        int c = t + 256 * i;
        int tile = c >> 9, rs = c & 511, row = rs >> 2, seg = rs & 3;
        const __nv_bfloat16* base;
        size_t grow;
        if (MODE == 1) {
            if (tile < 2) {
                base = tile ? g_xl : g_xh;
                grow = (size_t)(m0 + row) * 1280;
            } else {
                int g = e * 10240 + (row & 1) * 5120 + h0 + (row >> 1);
                base = (tile == 2) ? g_w1h : g_w1l;
                grow = (size_t)g * 1280;
            }
        } else {
            if (tile < 2) {
                base = tile ? g_hl : g_hh;
                grow = (size_t)(m0 + row) * 20480;
            } else {
                base = (tile == 2) ? g_w2h : g_w2l;
                grow = (size_t)(n0 + row) * 20480;
            }
        }
        gsrc[i] = base + grow + seg * 8;
        sdst[i] = sb + tile * TILE_B + row * 80 + seg * 16;
    }

#pragma unroll
    for (int st = 0; st < 2; st++) {
        size_t k0 = kbase + st * 32;
#pragma unroll
        for (int i = 0; i < 8; i++) CP_ASYNC16(sdst[i] + st * STAGE_B, gsrc[i] + k0);
        CP_COMMIT();
    }

    float cacc[2][8][4];
#pragma unroll
    for (int mf = 0; mf < 2; mf++)
#pragma unroll
        for (int nf = 0; nf < 8; nf++)
#pragma unroll
            for (int q = 0; q < 4; q++) cacc[mf][nf][q] = 0.f;

    unsigned warpM = (wid & 3) * 32;
    unsigned warpN = (wid >> 2) * 64;

    for (int kt = 0; kt < KT; kt++) {
        CP_WAIT1();
        __syncthreads();
        int st = kt & 1;
        unsigned sA_H = sb + st * STAGE_B;
        unsigned sA_L = sA_H + TILE_B;
        unsigned sB_H = sA_H + 2 * TILE_B;
        unsigned sB_L = sA_H + 3 * TILE_B;

#pragma unroll
        for (int ks = 0; ks < 2; ks++) {
            unsigned aH[2][4], aL[2][4];
#pragma unroll
            for (int mf = 0; mf < 2; mf++) {
                unsigned off = (warpM + mf * 16 + (lid & 15)) * 80 + ks * 32 + (lid >> 4) * 16;
                ldsm4(aH[mf], sA_H + off);
                ldsm4(aL[mf], sA_L + off);
            }
#pragma unroll
            for (int nf2 = 0; nf2 < 4; nf2++) {
                unsigned off = (warpN + nf2 * 16 + (lid & 7) + ((lid >> 4) & 1) * 8) * 80 +
                               ks * 32 + ((lid >> 3) & 1) * 16;
                unsigned rH[4], rL[4];
                ldsm4(rH, sB_H + off);
                ldsm4(rL, sB_L + off);
#pragma unroll
                for (int mf = 0; mf < 2; mf++) {
                    MMA16816(cacc[mf][2 * nf2],     aH[mf], rH[0], rH[1]);
                    MMA16816(cacc[mf][2 * nf2],     aH[mf], rL[0], rL[1]);
                    MMA16816(cacc[mf][2 * nf2],     aL[mf], rH[0], rH[1]);
                    MMA16816(cacc[mf][2 * nf2 + 1], aH[mf], rH[2], rH[3]);
                    MMA16816(cacc[mf][2 * nf2 + 1], aH[mf], rL[2], rL[3]);
                    MMA16816(cacc[mf][2 * nf2 + 1], aL[mf], rH[2], rH[3]);
                }
            }
        }
        __syncthreads();
        int ktn = kt + 2;
        if (ktn < KT) {
            size_t k0 = kbase + (size_t)ktn * 32;
#pragma unroll
            for (int i = 0; i < 8; i++) CP_ASYNC16(sdst[i] + st * STAGE_B, gsrc[i] + k0);
        }
        CP_COMMIT();
    }

    int grp = lid >> 2, qd = lid & 3;
    if (MODE == 1) {
        const float* bv = b1 + (size_t)e * 10240;
#pragma unroll
        for (int mf = 0; mf < 2; mf++) {
#pragma unroll
            for (int half = 0; half < 2; half++) {
                int n = m0 + warpM + mf * 16 + grp + half * 8;
                float gw = g_gw[n * 4 + e];
                size_t ob = (size_t)n * 20480 + (size_t)e * 5120;
#pragma unroll
                for (int nf = 0; nf < 8; nf++) {
                    int h = h0 + (warpN >> 1) + nf * 4 + qd;
                    float val  = cacc[mf][nf][half * 2 + 0];
                    float gate = cacc[mf][nf][half * 2 + 1];
                    float v = val + bv[h];
                    float g = gate + bv[5120 + h];
                    float hid = v * (0.5f * g * (1.f + erff(g * 0.70710678118654752f))) * gw;
                    __nv_bfloat16 hh = __float2bfloat16_rn(hid);
                    g_hh[ob + h] = hh;
                    g_hl[ob + h] = __float2bfloat16_rn(hid - __bfloat162float(hh));
                }
            }
        }
    } else {
        size_t zb = (size_t)blockIdx.z * 1310720;
#pragma unroll
        for (int mf = 0; mf < 2; mf++) {
#pragma unroll
            for (int half = 0; half < 2; half++) {
                int n = m0 + warpM + mf * 16 + grp + half * 8;
                size_t rb = zb + (size_t)n * 1280;
#pragma unroll
                for (int nf = 0; nf < 8; nf++) {
                    int col = n0 + warpN + nf * 8 + qd * 2;
                    g_part[rb + col]     = cacc[mf][nf][half * 2 + 0];
                    g_part[rb + col + 1] = cacc[mf][nf][half * 2 + 1];
                }
            }
        }
    }
}

// ================= split-K reduce + gated bias =================
__global__ void reduce_kernel(const float* __restrict__ b2, float* __restrict__ out) {
    int i = blockIdx.x * 256 + threadIdx.x;
    int n = i / 1280, j = i - n * 1280;
    float s = g_part[i] + g_part[1310720 + i] + g_part[2621440 + i] + g_part[3932160 + i];
    const float* gw = g_gw + n * 4;
    s += gw[0] * b2[j] + gw[1] * b2[1280 + j] + gw[2] * b2[2560 + j] + gw[3] * b2[3840 + j];
    out[i] = s;
}

// ================= launch =================
extern "C" void kernel_launch(void* const* d_in, const int* in_sizes, int n_in,
                              void* d_out, int out_size) {
    const float* x    = (const float*)d_in[0];
    const float* mask = (const float*)d_in[1];
    const float* c1w  = (const float*)d_in[2];
    const float* c1b  = (const float*)d_in[3];
    const float* bn1g = (const float*)d_in[4];
    const float* bn1b = (const float*)d_in[5];
    const float* bn1m = (const float*)d_in[6];
    const float* bn1v = (const float*)d_in[7];
    const float* c2w  = (const float*)d_in[8];
    const float* c2b  = (const float*)d_in[9];
    const float* bn2g = (const float*)d_in[10];
    const float* bn2b = (const float*)d_in[11];
    const float* bn2m = (const float*)d_in[12];
    const float* bn2v = (const float*)d_in[13];
    const float* c3w  = (const float*)d_in[14];
    const float* c3b  = (const float*)d_in[15];
    const float* bn3g = (const float*)d_in[16];
    const float* bn3b = (const float*)d_in[17];
    const float* bn3m = (const float*)d_in[18];
    const float* bn3v = (const float*)d_in[19];
    const float* fcw  = (const float*)d_in[20];
    const float* fcb  = (const float*)d_in[21];
    const float* w1   = (const float*)d_in[22];
    const float* b1   = (const float*)d_in[23];
    const float* w2   = (const float*)d_in[24];
    const float* b2   = (const float*)d_in[25];
    float* out = (float*)d_out;

    cudaFuncSetAttribute(mma_gemm_kernel<1>, cudaFuncAttributeMaxDynamicSharedMemorySize, SMEM_BYTES);
    cudaFuncSetAttribute(mma_gemm_kernel<2>, cudaFuncAttributeMaxDynamicSharedMemorySize, SMEM_BYTES);

    prep_kernel<2><<<216, 256>>>(c2w, c2b, bn2g, bn2b, bn2m, bn2v);
    prep_kernel<3><<<864, 256>>>(c3w, c3b, bn3g, bn3b, bn3m, bn3v);
    cvt_x_kernel<<<5120, 256>>>(x);
    trans_w1_kernel<<<dim3(320, 40, 4), dim3(32, 8)>>>(w1);
    trans_w2_kernel<<<dim3(40, 160, 4), dim3(32, 8)>>>(w2);
    conv1_kernel<<<dim3(1024, 8), 256>>>(mask, c1w, c1b, bn1g, bn1b, bn1m, bn1v);
    conv_gemm_kernel<2><<<dim3(256, 16, 1), 256>>>();
    conv_gemm_kernel<3><<<dim3(32, 16, 2), 256>>>();
    gate_kernel<<<1024, 128>>>(fcw, fcb);
    mma_gemm_kernel<1><<<dim3(8, 320), 256, SMEM_BYTES>>>(b1);
    mma_gemm_kernel<2><<<dim3(8, 10, 4), 256, SMEM_BYTES>>>(b1);
    reduce_kernel<<<5120, 256>>>(b2, out);
}